// round 3
// baseline (speedup 1.0000x reference)
#include <cuda_runtime.h>

// FractionalSTFT_42253888258226
//
// Identity (established R1, rel_err=1.6e-7): the fractional grid k2={j/16}
// is uniform over a full period -> W^H W = 16 I -> pinv(W) W = I -> the whole
// STFT/iSTFT/OLA pipeline reduces to out == x. Optimal kernel = 2 MiB D2D move.
//
// R3: R1 (512x256 kernel) and R2 (128x256, 4x float4/thread) measured
// identical total dur (6.6 vs 6.8us) -> we are at the graph-replay floor,
// not the copy's bandwidth/latency. Switch mechanism: a cudaMemcpyAsync
// D2D node (explicitly permitted, graph-capturable) lets the driver use
// its tuned copy path / copy engine instead of a user kernel node.

__global__ void fstft_copy_tail(const float* __restrict__ src,
                                float* __restrict__ dst,
                                int start, int n) {
    int i = start + blockIdx.x * blockDim.x + threadIdx.x;
    if (i < n) dst[i] = src[i];
}

extern "C" void kernel_launch(void* const* d_in, const int* in_sizes, int n_in,
                              void* d_out, int out_size) {
    const float* x = (const float*)d_in[0];   // (2, 2, 131072) fp32
    float* out = (float*)d_out;

    int n = out_size;                 // 524288
    if (n > in_sizes[0]) n = in_sizes[0];

    // Single D2D memcpy node on the capture (legacy default) stream.
    cudaMemcpyAsync(out, x, (size_t)n * sizeof(float),
                    cudaMemcpyDeviceToDevice, 0);

    // Generic guard (no-op for this shape): if out_size > input length,
    // the reference could never produce it; keep the copy exact anyway.
    (void)fstft_copy_tail;
}

// round 4
// speedup vs baseline: 1.0964x; 1.0964x over previous
#include <cuda_runtime.h>

// FractionalSTFT_42253888258226 — FINAL
//
// Identity (established R1, rel_err=1.56e-7): the fractional frequency grid
// k2 = {j/16 : j=0..16383} is uniform over one full period, so
//   (W^H W)[n,m] = (1/N) * sum_j exp(-i*2*pi*j*(n-m)/16384) = 16*delta_nm
// exactly. Hence pinv(W) = W^H/16 and pinv(W) @ W = I, so the analysis/
// synthesis pair is a perfect-reconstruction tight frame: y == frames.
// Overlap-add of window*xp divided by win_norm reconstructs xp; cropping
// [pad : pad+length] removes the reflect padding and the degenerate
// (win_norm -> 0) edges. The entire pipeline reduces to out == x.
//
// Floor analysis (R1-R3): a 512x256 float4 copy kernel, a 128x256 MLP=4
// copy kernel, and a cudaMemcpyAsync D2D node all measure 6.6-6.9us total.
// The 2 MiB move itself is <1us warm (L2-resident); the remainder is the
// harness's fixed graph-replay overhead. We are at the floor. This is the
// best-measured mechanism (R1), kept.

__global__ void fstft_copy_kernel(const float4* __restrict__ src,
                                  float4* __restrict__ dst,
                                  int n_vec4) {
    int i = blockIdx.x * blockDim.x + threadIdx.x;
    if (i < n_vec4) {
        dst[i] = src[i];
    }
}

__global__ void fstft_copy_tail(const float* __restrict__ src,
                                float* __restrict__ dst,
                                int start, int n) {
    int i = start + blockIdx.x * blockDim.x + threadIdx.x;
    if (i < n) dst[i] = src[i];
}

extern "C" void kernel_launch(void* const* d_in, const int* in_sizes, int n_in,
                              void* d_out, int out_size) {
    const float* x = (const float*)d_in[0];   // (2, 2, 131072) fp32
    float* out = (float*)d_out;

    int n = out_size;                 // 524288
    if (n > in_sizes[0]) n = in_sizes[0];

    int n_vec4 = n >> 2;              // 131072 float4 (16B-aligned: cudaMalloc'd)
    const int block = 256;
    int grid = (n_vec4 + block - 1) / block;   // 512
    if (grid > 0) {
        fstft_copy_kernel<<<grid, block>>>((const float4*)x, (float4*)out, n_vec4);
    }

    int done = n_vec4 << 2;
    if (n - done > 0) {               // 0 for this shape; generic safety
        fstft_copy_tail<<<1, 128>>>(x, out, done, n);
    }
}